// round 16
// baseline (speedup 1.0000x reference)
#include <cuda_runtime.h>

// Fixed problem shapes (QGenBelief reference)
#define B   64
#define Q   16
#define O   20
#define D   256
#define T   4096
#define D4  (D / 4)          // 64 float4 lanes per row
#define RPB 128              // t-rows per block
#define NTH 512              // threads per block (8 row-groups x 64 lanes)
#define RPT 16               // t-rows per thread (RPB / 8 row-groups) — optimum

__device__ __forceinline__ float fast_tanh(float x) {
    float y;
    asm("tanh.approx.f32 %0, %1;" : "=f"(y) : "f"(x));
    return y;
}

// ---------------------------------------------------------------------------
// Fused kernel: 512-thread block owns 128 consecutive t-rows of one batch.
// Per-thread store-run length stays at the measured-optimal 16 rows; block
// count halves (prologue amortization), belief compute is 2-way parallel
// across the wider block.
// ---------------------------------------------------------------------------
__global__ __launch_bounds__(NTH) void fused_kernel(
    const float* __restrict__ logits,  // [B,Q,O]
    const float* __restrict__ emb,     // [NUM_CAT,D]
    const int*   __restrict__ cats,    // [B,O]
    const int*   __restrict__ cum,     // [B,Q]
    const int*   __restrict__ nq,      // [B]
    float4*      __restrict__ out)     // [B,T,D] as float4
{
    const int b   = blockIdx.y;
    const int t0  = blockIdx.x * RPB;
    const int tid = threadIdx.x;

    __shared__ int   s_bnd[Q - 1];
    __shared__ int   s_nq;
    __shared__ int   s_qi[RPB];        // raw qi per row
    __shared__ int   s_cat[O];
    __shared__ float s_p[Q * O];       // softmax probs per distinct q
    __shared__ float s_bel[Q * D];     // belief rows for the block (16 KB max)

    if (tid < Q - 1)               s_bnd[tid]       = cum[b * Q + 1 + tid] - 1;
    if (tid == Q - 1)              s_nq             = nq[b];
    if (tid >= 32 && tid < 32 + O) s_cat[tid - 32]  = cats[b * O + (tid - 32)];
    __syncthreads();

    const int nqb = s_nq;

    if (tid < RPB) {
        const int t = t0 + tid;
        int qi = 0;
        #pragma unroll
        for (int j = 1; j < Q; ++j)
            if (j <= nqb - 1 && t >= s_bnd[j - 1]) qi++;
        s_qi[tid] = qi;
    }
    __syncthreads();

    const int qi0 = s_qi[0];
    const int qiL = min(s_qi[RPB - 1], nqb - 2);
    const int nd  = qiL - qi0 + 1;     // number of valid distinct questions

    if (nd > 0) {
        // Softmax for each distinct q: one thread each (20 elems, trivial).
        if (tid < nd) {
            const int q = qi0 + tid;
            float v[O];
            #pragma unroll
            for (int o = 0; o < O; ++o) v[o] = logits[(b * Q + q) * O + o];
            float m = v[0];
            #pragma unroll
            for (int o = 1; o < O; ++o) m = fmaxf(m, v[o]);
            float s = 0.f;
            #pragma unroll
            for (int o = 0; o < O; ++o) { v[o] = __expf(v[o] - m); s += v[o]; }
            const float inv = 1.f / s;
            #pragma unroll
            for (int o = 0; o < O; ++o) s_p[tid * O + o] = v[o] * inv;
        }
        __syncthreads();

        // Belief rows: half-blocks process alternate questions in parallel.
        // emb values are L1-broadcast between the two halves.
        const int d = tid & (D - 1);       // column 0..255
        const int h = tid >> 8;            // half-block id 0/1
        for (int c = h; c < nd; c += 2) {
            const float* pr = s_p + c * O;
            float acc = 0.f;
            #pragma unroll
            for (int o = 0; o < O; ++o)
                acc = fmaf(pr[o], emb[s_cat[o] * D + d], acc);
            s_bel[c * D + d] = fast_tanh(acc);
        }
    }
    __syncthreads();

    // Store stream: 8 row-groups x 64 float4 lanes; belief read from shared
    // only when qi changes. 16 rows per thread (measured-optimal run length).
    const int g  = tid >> 6;          // row-group 0..7
    const int d4 = tid & 63;          // float4 lane

    float4* o = out + ((size_t)b * T + t0 + g * RPT) * D4 + d4;

    int    prev = -2;
    float4 v = make_float4(0.f, 0.f, 0.f, 0.f);

    #pragma unroll
    for (int i = 0; i < RPT; ++i) {
        const int qraw = s_qi[g * RPT + i];           // warp-uniform
        const int key  = (qraw < nqb - 1) ? qraw : -1;
        if (key != prev) {
            prev = key;
            v = (key >= 0)
                ? *reinterpret_cast<const float4*>(&s_bel[(key - qi0) * D + d4 * 4])
                : make_float4(0.f, 0.f, 0.f, 0.f);
        }
        __stcs(o + i * D4, v);
    }
}

// ---------------------------------------------------------------------------
extern "C" void kernel_launch(void* const* d_in, const int* in_sizes, int n_in,
                              void* d_out, int out_size)
{
    const float* logits = (const float*)d_in[0];
    const float* emb    = (const float*)d_in[1];
    const int*   cats   = (const int*)d_in[2];
    const int*   cum    = (const int*)d_in[3];
    const int*   nq     = (const int*)d_in[4];

    dim3 grid(T / RPB, B);
    fused_kernel<<<grid, NTH>>>(logits, emb, cats, cum, nq, (float4*)d_out);
}

// round 17
// speedup vs baseline: 1.5147x; 1.5147x over previous
#include <cuda_runtime.h>

// Fixed problem shapes (QGenBelief reference)
#define B   64
#define Q   16
#define O   20
#define D   256
#define T   4096
#define D4  (D / 4)          // 64 float4 lanes per row
#define RPB 64               // t-rows per block (measured-optimal tile)
#define RPT 16               // t-rows per thread (RPB / 4 row-groups)

__device__ __forceinline__ float fast_tanh(float x) {
    float y;
    asm("tanh.approx.f32 %0, %1;" : "=f"(y) : "f"(x));
    return y;
}

// ---------------------------------------------------------------------------
// Fused kernel (final, locked config — benched 4x at ~41.2us kernel):
// each block owns 64 consecutive t-rows of one batch. qi is monotone in t,
// so the block needs beliefs for a contiguous range of questions [qi0, qiL]
// (usually 1-2). Compute them once into shared, then stream the 64 output
// rows with one float4 lane per thread. The 268 MB output write stream is
// the DRAM-bound floor; everything else hides under it.
// ---------------------------------------------------------------------------
__global__ __launch_bounds__(256) void fused_kernel(
    const float* __restrict__ logits,  // [B,Q,O]
    const float* __restrict__ emb,     // [NUM_CAT,D]
    const int*   __restrict__ cats,    // [B,O]
    const int*   __restrict__ cum,     // [B,Q]
    const int*   __restrict__ nq,      // [B]
    float4*      __restrict__ out)     // [B,T,D] as float4
{
    const int b   = blockIdx.y;
    const int t0  = blockIdx.x * RPB;
    const int tid = threadIdx.x;

    __shared__ int   s_bnd[Q - 1];
    __shared__ int   s_nq;
    __shared__ int   s_qi[RPB];        // raw qi per row
    __shared__ int   s_cat[O];
    __shared__ float s_p[Q * O];       // softmax probs per distinct q
    __shared__ float s_bel[Q * D];     // belief rows for the block (16 KB max)

    if (tid < Q - 1)               s_bnd[tid]       = cum[b * Q + 1 + tid] - 1;
    if (tid == Q - 1)              s_nq             = nq[b];
    if (tid >= 32 && tid < 32 + O) s_cat[tid - 32]  = cats[b * O + (tid - 32)];
    __syncthreads();

    const int nqb = s_nq;

    if (tid < RPB) {
        const int t = t0 + tid;
        int qi = 0;
        #pragma unroll
        for (int j = 1; j < Q; ++j)
            if (j <= nqb - 1 && t >= s_bnd[j - 1]) qi++;
        s_qi[tid] = qi;
    }
    __syncthreads();

    const int qi0 = s_qi[0];
    const int qiL = min(s_qi[RPB - 1], nqb - 2);
    const int nd  = qiL - qi0 + 1;     // number of valid distinct questions

    if (nd > 0) {
        // Softmax for each distinct q: one thread each (20 elems, trivial).
        if (tid < nd) {
            const int q = qi0 + tid;
            float v[O];
            #pragma unroll
            for (int o = 0; o < O; ++o) v[o] = logits[(b * Q + q) * O + o];
            float m = v[0];
            #pragma unroll
            for (int o = 1; o < O; ++o) m = fmaxf(m, v[o]);
            float s = 0.f;
            #pragma unroll
            for (int o = 0; o < O; ++o) { v[o] = __expf(v[o] - m); s += v[o]; }
            const float inv = 1.f / s;
            #pragma unroll
            for (int o = 0; o < O; ++o) s_p[tid * O + o] = v[o] * inv;
        }
        __syncthreads();

        // Belief rows: single pass over emb (each value loaded once per block),
        // accumulating up to 4 questions at a time.
        for (int c0 = 0; c0 < nd; c0 += 4) {
            const int cn = min(4, nd - c0);
            float acc[4] = {0.f, 0.f, 0.f, 0.f};
            #pragma unroll
            for (int o = 0; o < O; ++o) {
                const float e = emb[s_cat[o] * D + tid];
                #pragma unroll
                for (int k = 0; k < 4; ++k)
                    if (k < cn) acc[k] = fmaf(s_p[(c0 + k) * O + o], e, acc[k]);
            }
            #pragma unroll
            for (int k = 0; k < 4; ++k)
                if (k < cn) s_bel[(c0 + k) * D + tid] = fast_tanh(acc[k]);
        }
    }
    __syncthreads();

    // Store stream: 4 row-groups x 64 float4 lanes; belief read from shared
    // only when qi changes.
    const int g  = tid >> 6;
    const int d4 = tid & 63;

    float4* o = out + ((size_t)b * T + t0 + g * RPT) * D4 + d4;

    int    prev = -2;
    float4 v = make_float4(0.f, 0.f, 0.f, 0.f);

    #pragma unroll
    for (int i = 0; i < RPT; ++i) {
        const int qraw  = s_qi[g * RPT + i];          // warp-uniform
        const int key   = (qraw < nqb - 1) ? qraw : -1;
        if (key != prev) {
            prev = key;
            v = (key >= 0)
                ? *reinterpret_cast<const float4*>(&s_bel[(key - qi0) * D + d4 * 4])
                : make_float4(0.f, 0.f, 0.f, 0.f);
        }
        __stcs(o + i * D4, v);
    }
}

// ---------------------------------------------------------------------------
extern "C" void kernel_launch(void* const* d_in, const int* in_sizes, int n_in,
                              void* d_out, int out_size)
{
    const float* logits = (const float*)d_in[0];
    const float* emb    = (const float*)d_in[1];
    const int*   cats   = (const int*)d_in[2];
    const int*   cum    = (const int*)d_in[3];
    const int*   nq     = (const int*)d_in[4];

    dim3 grid(T / RPB, B);
    fused_kernel<<<grid, 256>>>(logits, emb, cats, cum, nq, (float4*)d_out);
}